// round 5
// baseline (speedup 1.0000x reference)
#include <cuda_runtime.h>
#include <math.h>

#define BB 64
#define TT 512
#define HH 512
#define GG 2048          // 4*H
#define RECBLK 128
#define RECTHR 256

// ---- scratch (static device allocations; no cudaMalloc allowed) ----
__device__ float g_G[67108864];   // [t*64+b][2048] precomputed input gates + biases (268 MB)
__device__ float g_H0[16777216];  // layer-0 outputs [t*64+b][512] (64 MB)
__device__ float g_hT[32768];     // transposed h state [u][b]
__device__ float g_c[32768];      // c state [b][u]
__device__ float g_P[524288];     // per-step partial gate sums [kb][b][n] (2 MB)
__device__ unsigned g_barGen = 0;
__device__ unsigned g_barCnt = 0;

// ---- grid-wide barrier (all RECBLK CTAs co-resident) ----
__device__ __forceinline__ void gridBarrier() {
    __syncthreads();
    if (threadIdx.x == 0) {
        volatile unsigned* vgen = &g_barGen;
        unsigned g = *vgen;
        __threadfence();                       // publish my writes (also L1 invalidate scope)
        unsigned old = atomicAdd(&g_barCnt, 1u);
        if (old == (unsigned)(RECBLK - 1)) {
            g_barCnt = 0u;
            __threadfence();
            *vgen = g + 1u;                    // release
        } else {
            while (*vgen == g) { }             // volatile spin (bypasses L1)
        }
        __threadfence();                       // acquire: invalidate stale L1 lines
    }
    __syncthreads();
}

__device__ __forceinline__ float sigmoidf_(float x) {
    return 1.0f / (1.0f + __expf(-x));
}

// ============================================================
// Precompute GEMM: G[r][n] = inp_row(r) . Wih[n][:] + bih[n] + bhh[n]
// M = 32768 (r = t*64+b), N = 2048, K = 512.
// Block 128x128, 256 threads, 8x8 microtile, BK=16.
// ============================================================
__global__ void __launch_bounds__(256) lstm_pregemm(
    const float* __restrict__ xin,   // x for layer0; unused for layer1 (reads g_H0)
    const float* __restrict__ Wih,
    const float* __restrict__ bih,
    const float* __restrict__ bhh,
    int layer0)
{
    __shared__ float As[16][128];
    __shared__ float Bsh[16][128];
    const int tid = threadIdx.x;
    const int colblk = blockIdx.x * 128;
    const int rowblk = blockIdx.y * 128;
    const int tx = tid & 15;
    const int ty = tid >> 4;

    float acc[8][8];
    #pragma unroll
    for (int i = 0; i < 8; ++i)
        #pragma unroll
        for (int j = 0; j < 8; ++j) acc[i][j] = 0.0f;

    for (int kc = 0; kc < 512; kc += 16) {
        // stage A tile (transpose to [k][m]); layer0 remaps row r=t*64+b -> x[b][t][:]
        #pragma unroll
        for (int jj = 0; jj < 2; ++jj) {
            int e = tid + jj * 256;
            int r = e >> 2;
            int kq = e & 3;
            int rg = rowblk + r;
            const float* src = layer0
                ? (xin + (size_t)(((rg & 63) << 9) + (rg >> 6)) * 512)
                : (g_H0 + (size_t)rg * 512);
            float4 v = *(const float4*)(src + kc + kq * 4);
            As[kq*4+0][r] = v.x; As[kq*4+1][r] = v.y;
            As[kq*4+2][r] = v.z; As[kq*4+3][r] = v.w;
        }
        // stage B tile (Wih rows are k-contiguous; transpose to [k][n])
        #pragma unroll
        for (int jj = 0; jj < 2; ++jj) {
            int e = tid + jj * 256;
            int n = e >> 2;
            int kq = e & 3;
            float4 v = *(const float4*)(Wih + (size_t)(colblk + n) * 512 + kc + kq * 4);
            Bsh[kq*4+0][n] = v.x; Bsh[kq*4+1][n] = v.y;
            Bsh[kq*4+2][n] = v.z; Bsh[kq*4+3][n] = v.w;
        }
        __syncthreads();
        #pragma unroll
        for (int k = 0; k < 16; ++k) {
            float a[8], b2[8];
            *(float4*)(a)     = *(const float4*)&As[k][tx * 8];
            *(float4*)(a + 4) = *(const float4*)&As[k][tx * 8 + 4];
            *(float4*)(b2)     = *(const float4*)&Bsh[k][ty * 8];
            *(float4*)(b2 + 4) = *(const float4*)&Bsh[k][ty * 8 + 4];
            #pragma unroll
            for (int i = 0; i < 8; ++i)
                #pragma unroll
                for (int j = 0; j < 8; ++j)
                    acc[i][j] = fmaf(a[i], b2[j], acc[i][j]);
        }
        __syncthreads();
    }

    float bsum[8];
    #pragma unroll
    for (int j = 0; j < 8; ++j) {
        int n = colblk + ty * 8 + j;
        bsum[j] = bih[n] + bhh[n];
    }
    #pragma unroll
    for (int i = 0; i < 8; ++i) {
        int r = rowblk + tx * 8 + i;
        float* dst = g_G + (size_t)r * GG + colblk + ty * 8;
        float4 v0 = make_float4(acc[i][0]+bsum[0], acc[i][1]+bsum[1],
                                acc[i][2]+bsum[2], acc[i][3]+bsum[3]);
        float4 v1 = make_float4(acc[i][4]+bsum[4], acc[i][5]+bsum[5],
                                acc[i][6]+bsum[6], acc[i][7]+bsum[7]);
        *(float4*)dst = v0;
        *(float4*)(dst + 4) = v1;
    }
}

// ============================================================
// Persistent recurrent kernel (one launch per layer).
// 128 CTAs: CTA (nb = bid&31, kb = bid>>5) computes the partial
// gates[b, nb*64 .. +64) over k in [kb*128, +128).
// Whh tile (64 cols x 128 k = 32 KB) resident in SMEM for all 512 steps.
// Per step: phase A (partial GEMM -> g_P), barrier, phase B (cell), barrier.
// ============================================================
__global__ void __launch_bounds__(RECTHR) lstm_recurrent(
    const float* __restrict__ Whh,
    const float* __restrict__ h0,
    const float* __restrict__ c0,
    float* __restrict__ outSeq,   // layer1: output [b][t][u]; layer0: unused (writes g_H0)
    float* __restrict__ hfin,
    float* __restrict__ cfin,
    int layer1)
{
    __shared__ float Bs[128 * 64];   // [k][n] transposed weight tile
    const int tid = threadIdx.x;
    const int bid = blockIdx.x;
    const int nb = bid & 31;
    const int kb = bid >> 5;
    const int tx = tid & 15;   // m-group (4 batch rows)
    const int ty = tid >> 4;   // n-group (4 cols)

    // init state (32768 elements, 1 per thread)
    {
        int idx = bid * RECTHR + tid;
        int b = idx >> 9;
        int u = idx & 511;
        g_hT[u * BB + b] = h0[b * HH + u];
        g_c[b * HH + u]  = c0[b * HH + u];
    }
    // load persistent weight tile (transposed); one-time cost
    for (int e = tid; e < 64 * 128; e += RECTHR) {
        int n = e >> 7;
        int k = e & 127;
        Bs[k * 64 + n] = Whh[(size_t)(nb * 64 + n) * 512 + kb * 128 + k];
    }
    gridBarrier();

    const float* aCol = g_hT + kb * 128 * BB + tx * 4;  // h^T slice: [k][b], b contiguous
    const float* bCol = Bs + ty * 4;

    for (int t = 0; t < TT; ++t) {
        // ---- phase A: partial GEMM  M=64 x N=64 x K=128 ----
        float acc[4][4];
        #pragma unroll
        for (int i = 0; i < 4; ++i)
            #pragma unroll
            for (int j = 0; j < 4; ++j) acc[i][j] = 0.0f;

        #pragma unroll 8
        for (int k = 0; k < 128; ++k) {
            float4 av = *(const float4*)(aCol + k * 64);  // coalesced, L1-resident
            float4 bv = *(const float4*)(bCol + k * 64);  // SMEM broadcast
            float aa[4]  = {av.x, av.y, av.z, av.w};
            float bb2[4] = {bv.x, bv.y, bv.z, bv.w};
            #pragma unroll
            for (int i = 0; i < 4; ++i)
                #pragma unroll
                for (int j = 0; j < 4; ++j)
                    acc[i][j] = fmaf(aa[i], bb2[j], acc[i][j]);
        }
        #pragma unroll
        for (int i = 0; i < 4; ++i) {
            float4 v = make_float4(acc[i][0], acc[i][1], acc[i][2], acc[i][3]);
            *(float4*)(g_P + (kb * 64 + tx * 4 + i) * GG + nb * 64 + ty * 4) = v;
        }
        gridBarrier();

        // ---- phase B: cell update (1 cell per thread) ----
        {
            int idx = bid * RECTHR + tid;
            int b = idx >> 9;
            int u = idx & 511;
            const float* gRow = g_G + (size_t)(t * BB + b) * GG;
            float s[4];
            #pragma unroll
            for (int g = 0; g < 4; ++g) {
                float v = gRow[g * 512 + u];
                #pragma unroll
                for (int kk = 0; kk < 4; ++kk)
                    v += g_P[(kk * 64 + b) * GG + g * 512 + u];
                s[g] = v;
            }
            float iv = sigmoidf_(s[0]);
            float fv = sigmoidf_(s[1]);
            float gv = tanhf(s[2]);
            float ov = sigmoidf_(s[3]);
            float cv = fv * g_c[b * HH + u] + iv * gv;
            float hv = ov * tanhf(cv);
            g_c[b * HH + u] = cv;
            g_hT[u * BB + b] = hv;
            if (layer1) outSeq[(size_t)(b * TT + t) * HH + u] = hv;
            else        g_H0[(size_t)(t * BB + b) * HH + u] = hv;
            if (t == TT - 1) {
                hfin[b * HH + u] = hv;
                cfin[b * HH + u] = cv;
            }
        }
        gridBarrier();
    }
}

// ============================================================
// kernel_launch: 4 graph-capturable launches, no allocations.
// Output layout: out [B,T,H] ++ h_fin [2,B,H] ++ c_fin [2,B,H]
// ============================================================
extern "C" void kernel_launch(void* const* d_in, const int* in_sizes, int n_in,
                              void* d_out, int out_size)
{
    (void)in_sizes; (void)n_in; (void)out_size;
    const float* x   = (const float*)d_in[0];
    const float* h0  = (const float*)d_in[1];
    const float* c0  = (const float*)d_in[2];
    const float* Wih = (const float*)d_in[3];
    const float* Whh = (const float*)d_in[4];
    const float* bih = (const float*)d_in[5];
    const float* bhh = (const float*)d_in[6];
    float* out  = (float*)d_out;
    float* hfin = out + (size_t)BB * TT * HH;
    float* cfin = hfin + 2 * BB * HH;

    dim3 pgrid(GG / 128, (BB * TT) / 128);  // (16, 256)

    // layer 0
    lstm_pregemm<<<pgrid, 256>>>(x, Wih, bih, bhh, 1);
    lstm_recurrent<<<RECBLK, RECTHR>>>(Whh, h0, c0, nullptr, hfin, cfin, 0);
    // layer 1
    lstm_pregemm<<<pgrid, 256>>>(x, Wih + (size_t)GG * 512, bih + GG, bhh + GG, 0);
    lstm_recurrent<<<RECBLK, RECTHR>>>(Whh + (size_t)GG * 512, h0 + BB * HH, c0 + BB * HH,
                                       out, hfin + BB * HH, cfin + BB * HH, 1);
}

// round 6
// speedup vs baseline: 1.9407x; 1.9407x over previous
#include <cuda_runtime.h>
#include <math.h>

#define BB 64
#define TT 512
#define HH 512
#define GG 2048          // 4*H
#define RECBLK 128
#define RECTHR 256

// ---- static device scratch (no cudaMalloc allowed) ----
__device__ float g_G[67108864];    // G^T: [col 0..2048)[r=t*64+b 0..32768)  (268 MB)
__device__ float g_H0T[16777216];  // layer-0 output archive: [u][r]          (64 MB)
__device__ float g_h[65536];       // h state double buffer: 2 x [b][u]
__device__ unsigned g_leaf[8 * 64];  // 8 leaf counters, 256B apart
__device__ unsigned g_root;
__device__ unsigned g_gen;

// ---- monotonic 2-level grid barrier (replay-safe: no resets) ----
__device__ __forceinline__ void gridBarrier() {
    __syncthreads();
    if (threadIdx.x == 0) {
        asm volatile("membar.gl;" ::: "memory");
        volatile unsigned* vgen = &g_gen;
        unsigned g = *vgen;
        unsigned leaf = (blockIdx.x >> 4) << 6;
        unsigned old = atomicAdd(&g_leaf[leaf], 1u);
        if (old == g * 16u + 15u) {
            unsigned old2 = atomicAdd(&g_root, 1u);
            if (old2 == g * 8u + 7u) {
                *vgen = g + 1u;                 // release
            } else {
                while (*vgen == g) { }
            }
        } else {
            while (*vgen == g) { }
        }
    }
    __syncthreads();
}

__device__ __forceinline__ void cpasync16(float* dst_smem, const float* src) {
    unsigned d = (unsigned)__cvta_generic_to_shared(dst_smem);
    asm volatile("cp.async.cg.shared.global [%0], [%1], 16;" :: "r"(d), "l"(src));
}

__device__ __forceinline__ float sigmoidf_(float x) {
    return 1.0f / (1.0f + __expf(-x));
}

// ============================================================
// Precompute GEMM (transposed output):
//   Gt[col][r] = W[col][:] . Xrow(r)[:] + bih[col] + bhh[col]
//   M = col = 2048, N = r = 32768, K = 512.
// layer0: Xrow(r) = x[b][t][:], r = t*64+b (transposing stage)
// layer1: Xrow(r) = H0T[:, r]  ([k][r] layout — direct stage)
// ============================================================
__global__ void __launch_bounds__(256) lstm_pregemm(
    const float* __restrict__ xin,
    const float* __restrict__ Wih,
    const float* __restrict__ bih,
    const float* __restrict__ bhh,
    int layer0)
{
    __shared__ float As[16][128];   // [k][m=col]
    __shared__ float Bs[16][128];   // [k][n=r]
    const int tid = threadIdx.x;
    const int rblk = blockIdx.x * 128;   // n
    const int mblk = blockIdx.y * 128;   // m (col)
    const int nx = tid & 15;
    const int mx = tid >> 4;

    float acc[8][8];
    #pragma unroll
    for (int i = 0; i < 8; ++i)
        #pragma unroll
        for (int j = 0; j < 8; ++j) acc[i][j] = 0.0f;

    for (int kc = 0; kc < 512; kc += 16) {
        // stage A: W rows (k-contiguous) -> As[k][m]
        #pragma unroll
        for (int jj = 0; jj < 2; ++jj) {
            int e = tid + jj * 256;
            int m = e >> 2;
            int kq = e & 3;
            float4 v = *(const float4*)(Wih + (size_t)(mblk + m) * 512 + kc + kq * 4);
            As[kq*4+0][m] = v.x; As[kq*4+1][m] = v.y;
            As[kq*4+2][m] = v.z; As[kq*4+3][m] = v.w;
        }
        // stage B
        if (layer0) {
            #pragma unroll
            for (int jj = 0; jj < 2; ++jj) {
                int e = tid + jj * 256;
                int n = e >> 2;
                int kq = e & 3;
                int r = rblk + n;
                const float* src = xin + (size_t)(((r & 63) << 9) + (r >> 6)) * 512;
                float4 v = *(const float4*)(src + kc + kq * 4);
                Bs[kq*4+0][n] = v.x; Bs[kq*4+1][n] = v.y;
                Bs[kq*4+2][n] = v.z; Bs[kq*4+3][n] = v.w;
            }
        } else {
            #pragma unroll
            for (int jj = 0; jj < 2; ++jj) {
                int e = tid + jj * 256;
                int k = e >> 5;
                int nq = e & 31;
                *(float4*)&Bs[k][nq * 4] =
                    *(const float4*)(g_H0T + (size_t)(kc + k) * 32768 + rblk + nq * 4);
            }
        }
        __syncthreads();
        #pragma unroll
        for (int k = 0; k < 16; ++k) {
            float a[8], b2[8];
            *(float4*)(a)      = *(const float4*)&As[k][mx * 8];
            *(float4*)(a + 4)  = *(const float4*)&As[k][mx * 8 + 4];
            *(float4*)(b2)     = *(const float4*)&Bs[k][nx * 8];
            *(float4*)(b2 + 4) = *(const float4*)&Bs[k][nx * 8 + 4];
            #pragma unroll
            for (int i = 0; i < 8; ++i)
                #pragma unroll
                for (int j = 0; j < 8; ++j)
                    acc[i][j] = fmaf(a[i], b2[j], acc[i][j]);
        }
        __syncthreads();
    }

    float bsum[8];
    #pragma unroll
    for (int i = 0; i < 8; ++i) {
        int col = mblk + mx * 8 + i;
        bsum[i] = bih[col] + bhh[col];
    }
    #pragma unroll
    for (int i = 0; i < 8; ++i) {
        float* dst = g_G + (size_t)(mblk + mx * 8 + i) * 32768 + rblk + nx * 8;
        float4 v0 = make_float4(acc[i][0]+bsum[i], acc[i][1]+bsum[i],
                                acc[i][2]+bsum[i], acc[i][3]+bsum[i]);
        float4 v1 = make_float4(acc[i][4]+bsum[i], acc[i][5]+bsum[i],
                                acc[i][6]+bsum[i], acc[i][7]+bsum[i]);
        *(float4*)dst = v0;
        *(float4*)(dst + 4) = v1;
    }
}

// ============================================================
// Persistent recurrent kernel: 128 CTAs x 256 threads, one launch per layer.
// CTA j owns hidden units u0 = 4j .. 4j+3 (16 gate-cols), full K=512, all 64 b.
// One grid barrier per step. c state lives in registers.
// SMEM: hs[64][516] staged h, Wt[512][16] weights, gsum[64][17] gate exchange.
// ============================================================
__global__ void __launch_bounds__(RECTHR, 1) lstm_recurrent(
    const float* __restrict__ Whh,
    const float* __restrict__ h0,
    const float* __restrict__ c0,
    float* __restrict__ outSeq,   // layer1: [b][t][u]; layer0: null (writes g_H0T)
    float* __restrict__ hfin,
    float* __restrict__ cfin,
    int layer1)
{
    extern __shared__ float smem[];
    float* hs   = smem;                  // [64][516]  (pad 4 to kill bank conflicts)
    float* Wt   = smem + 64 * 516;       // [512][16]
    float* gsum = Wt + 512 * 16;         // [64][17]

    const int tid = threadIdx.x;
    const int bid = blockIdx.x;
    const int u0  = bid * 4;
    const int w   = tid >> 5;
    const int l   = tid & 31;
    const int bG  = w * 8 + (l >> 2);    // GEMM batch row (1 per lane)
    const int cg  = l & 3;               // GEMM col group (4 cols)
    const int bC  = tid & 63;            // cell batch
    const int uu  = tid >> 6;            // cell unit offset (0..3)

    // persistent weight tile: Wt[k][c], c = g*4 + j, row = g*512 + u0 + j
    for (int e = tid; e < 16 * 512; e += RECTHR) {
        int c = e >> 9;
        int k = e & 511;
        int g = c >> 2, j = c & 3;
        Wt[k * 16 + c] = Whh[(size_t)(g * 512 + u0 + j) * 512 + k];
    }

    // init state: h -> buffer 0 ([b][u]); c -> register
    {
        int idx = bid * RECTHR + tid;      // 32768
        __stcg(&g_h[idx], h0[idx]);
    }
    float c_reg = c0[bC * HH + u0 + uu];

    gridBarrier();

    for (int t = 0; t < TT; ++t) {
        const float* hRead = g_h + (t & 1) * 32768;
        float* hWrite      = g_h + ((t + 1) & 1) * 32768;

        // ---- stage my warp's 8 h rows into SMEM (cp.async.cg, L2-coherent) ----
        {
            int row = w * 8 + (l >> 2);
            int q   = l & 3;
            const float* src = hRead + row * 512 + q * 128;
            float* dst = hs + row * 516 + q * 128;
            #pragma unroll
            for (int i = 0; i < 32; ++i) cpasync16(dst + i * 4, src + i * 4);
            asm volatile("cp.async.commit_group;");
            asm volatile("cp.async.wait_group 0;" ::: "memory");
            __syncwarp();
        }

        // ---- GEMM: acc[c] = sum_k h[bG][k] * Wt[k][cg*4+c] ----
        float a0 = 0.f, a1 = 0.f, a2 = 0.f, a3 = 0.f;
        const float* hrow = hs + bG * 516;
        const float* wcol = Wt + cg * 4;
        #pragma unroll 4
        for (int k = 0; k < 512; k += 4) {
            float4 hv = *(const float4*)(hrow + k);
            #pragma unroll
            for (int kk = 0; kk < 4; ++kk) {
                float4 wv = *(const float4*)(wcol + (size_t)(k + kk) * 16);
                float h = (&hv.x)[kk];
                a0 = fmaf(h, wv.x, a0);
                a1 = fmaf(h, wv.y, a1);
                a2 = fmaf(h, wv.z, a2);
                a3 = fmaf(h, wv.w, a3);
            }
        }
        {
            float* gs = gsum + bG * 17 + cg * 4;
            gs[0] = a0; gs[1] = a1; gs[2] = a2; gs[3] = a3;
        }
        __syncthreads();

        // ---- cell update (thread owns (bC, u0+uu); c in register) ----
        {
            float s[4];
            #pragma unroll
            for (int g = 0; g < 4; ++g) {
                float recur = gsum[bC * 17 + g * 4 + uu];
                float pre = __ldcs(g_G + (size_t)(g * 512 + u0 + uu) * 32768
                                       + (size_t)t * 64 + bC);
                s[g] = recur + pre;
            }
            float iv = sigmoidf_(s[0]);
            float fv = sigmoidf_(s[1]);
            float gv = tanhf(s[2]);
            float ov = sigmoidf_(s[3]);
            c_reg = fv * c_reg + iv * gv;
            float hv = ov * tanhf(c_reg);

            __stcg(&hWrite[bC * HH + u0 + uu], hv);
            if (layer1) outSeq[((size_t)bC * TT + t) * HH + u0 + uu] = hv;
            else        __stcg(&g_H0T[(size_t)(u0 + uu) * 32768 + (size_t)t * 64 + bC], hv);
            if (t == TT - 1) {
                hfin[bC * HH + u0 + uu] = hv;
                cfin[bC * HH + u0 + uu] = c_reg;
            }
        }
        gridBarrier();
    }
}

// ============================================================
// kernel_launch: 4 graph-capturable launches.
// Output: out [B,T,H] ++ h_fin [2,B,H] ++ c_fin [2,B,H]
// ============================================================
extern "C" void kernel_launch(void* const* d_in, const int* in_sizes, int n_in,
                              void* d_out, int out_size)
{
    (void)in_sizes; (void)n_in; (void)out_size;
    const float* x   = (const float*)d_in[0];
    const float* h0  = (const float*)d_in[1];
    const float* c0  = (const float*)d_in[2];
    const float* Wih = (const float*)d_in[3];
    const float* Whh = (const float*)d_in[4];
    const float* bih = (const float*)d_in[5];
    const float* bhh = (const float*)d_in[6];
    float* out  = (float*)d_out;
    float* hfin = out + (size_t)BB * TT * HH;
    float* cfin = hfin + 2 * BB * HH;

    const int recSmem = (64 * 516 + 512 * 16 + 64 * 17) * (int)sizeof(float);
    cudaFuncSetAttribute(lstm_recurrent,
                         cudaFuncAttributeMaxDynamicSharedMemorySize, recSmem);

    dim3 pgrid(32768 / 128, GG / 128);   // (256, 16)

    // layer 0
    lstm_pregemm<<<pgrid, 256>>>(x, Wih, bih, bhh, 1);
    lstm_recurrent<<<RECBLK, RECTHR, recSmem>>>(Whh, h0, c0, nullptr, hfin, cfin, 0);
    // layer 1 (input GEMM reads g_H0T directly)
    lstm_pregemm<<<pgrid, 256>>>(x, Wih + (size_t)GG * 512, bih + GG, bhh + GG, 0);
    lstm_recurrent<<<RECBLK, RECTHR, recSmem>>>(Whh + (size_t)GG * 512,
                                                h0 + BB * HH, c0 + BB * HH,
                                                out, hfin + BB * HH, cfin + BB * HH, 1);
}

// round 7
// speedup vs baseline: 2.2783x; 1.1739x over previous
#include <cuda_runtime.h>
#include <math.h>

#define BB 64
#define TT 512
#define HH 512
#define GG 2048          // 4*H
#define RECBLK 128
#define RECTHR 256

// ---- static device scratch (no cudaMalloc allowed) ----
__device__ float g_G[67108864];    // G^T: [col 0..2048)[r=t*64+b 0..32768)  (268 MB)
__device__ float g_H0T[16777216];  // layer-0 output archive: [u][r]          (64 MB)
__device__ float g_h[65536];       // h state double buffer: 2 x [b][u]
__device__ unsigned g_leaf[8 * 64];  // 8 leaf counters, 256B apart
__device__ unsigned g_root;
__device__ unsigned g_gen;

// ---- monotonic 2-level grid barrier (replay-safe: no resets) ----
__device__ __forceinline__ void gridBarrier() {
    __syncthreads();
    if (threadIdx.x == 0) {
        asm volatile("membar.gl;" ::: "memory");
        volatile unsigned* vgen = &g_gen;
        unsigned g = *vgen;
        unsigned leaf = (blockIdx.x >> 4) << 6;
        unsigned old = atomicAdd(&g_leaf[leaf], 1u);
        if (old == g * 16u + 15u) {
            unsigned old2 = atomicAdd(&g_root, 1u);
            if (old2 == g * 8u + 7u) {
                *vgen = g + 1u;                 // release
            } else {
                while (*vgen == g) { }
            }
        } else {
            while (*vgen == g) { }
        }
    }
    __syncthreads();
}

__device__ __forceinline__ float sigmoidf_(float x) {
    return 1.0f / (1.0f + __expf(-x));
}

__device__ __forceinline__ unsigned smem_u32(const void* p) {
    unsigned a;
    asm("{ .reg .u64 t; cvta.to.shared.u64 t, %1; cvt.u32.u64 %0, t; }"
        : "=r"(a) : "l"(p));
    return a;
}

// ============================================================
// Precompute GEMM (transposed output) — unchanged from round 6.
//   Gt[col][r] = W[col][:] . Xrow(r)[:] + bih[col] + bhh[col]
// ============================================================
__global__ void __launch_bounds__(256) lstm_pregemm(
    const float* __restrict__ xin,
    const float* __restrict__ Wih,
    const float* __restrict__ bih,
    const float* __restrict__ bhh,
    int layer0)
{
    __shared__ float As[16][128];   // [k][m=col]
    __shared__ float Bs[16][128];   // [k][n=r]
    const int tid = threadIdx.x;
    const int rblk = blockIdx.x * 128;   // n
    const int mblk = blockIdx.y * 128;   // m (col)
    const int nx = tid & 15;
    const int mx = tid >> 4;

    float acc[8][8];
    #pragma unroll
    for (int i = 0; i < 8; ++i)
        #pragma unroll
        for (int j = 0; j < 8; ++j) acc[i][j] = 0.0f;

    for (int kc = 0; kc < 512; kc += 16) {
        #pragma unroll
        for (int jj = 0; jj < 2; ++jj) {
            int e = tid + jj * 256;
            int m = e >> 2;
            int kq = e & 3;
            float4 v = *(const float4*)(Wih + (size_t)(mblk + m) * 512 + kc + kq * 4);
            As[kq*4+0][m] = v.x; As[kq*4+1][m] = v.y;
            As[kq*4+2][m] = v.z; As[kq*4+3][m] = v.w;
        }
        if (layer0) {
            #pragma unroll
            for (int jj = 0; jj < 2; ++jj) {
                int e = tid + jj * 256;
                int n = e >> 2;
                int kq = e & 3;
                int r = rblk + n;
                const float* src = xin + (size_t)(((r & 63) << 9) + (r >> 6)) * 512;
                float4 v = *(const float4*)(src + kc + kq * 4);
                Bs[kq*4+0][n] = v.x; Bs[kq*4+1][n] = v.y;
                Bs[kq*4+2][n] = v.z; Bs[kq*4+3][n] = v.w;
            }
        } else {
            #pragma unroll
            for (int jj = 0; jj < 2; ++jj) {
                int e = tid + jj * 256;
                int k = e >> 5;
                int nq = e & 31;
                *(float4*)&Bs[k][nq * 4] =
                    *(const float4*)(g_H0T + (size_t)(kc + k) * 32768 + rblk + nq * 4);
            }
        }
        __syncthreads();
        #pragma unroll
        for (int k = 0; k < 16; ++k) {
            float a[8], b2[8];
            *(float4*)(a)      = *(const float4*)&As[k][mx * 8];
            *(float4*)(a + 4)  = *(const float4*)&As[k][mx * 8 + 4];
            *(float4*)(b2)     = *(const float4*)&Bs[k][nx * 8];
            *(float4*)(b2 + 4) = *(const float4*)&Bs[k][nx * 8 + 4];
            #pragma unroll
            for (int i = 0; i < 8; ++i)
                #pragma unroll
                for (int j = 0; j < 8; ++j)
                    acc[i][j] = fmaf(a[i], b2[j], acc[i][j]);
        }
        __syncthreads();
    }

    float bsum[8];
    #pragma unroll
    for (int i = 0; i < 8; ++i) {
        int col = mblk + mx * 8 + i;
        bsum[i] = bih[col] + bhh[col];
    }
    #pragma unroll
    for (int i = 0; i < 8; ++i) {
        float* dst = g_G + (size_t)(mblk + mx * 8 + i) * 32768 + rblk + nx * 8;
        float4 v0 = make_float4(acc[i][0]+bsum[i], acc[i][1]+bsum[i],
                                acc[i][2]+bsum[i], acc[i][3]+bsum[i]);
        float4 v1 = make_float4(acc[i][4]+bsum[i], acc[i][5]+bsum[i],
                                acc[i][6]+bsum[i], acc[i][7]+bsum[i]);
        *(float4*)dst = v0;
        *(float4*)(dst + 4) = v1;
    }
}

// ============================================================
// Persistent recurrent kernel v3: 128 CTAs x 256 threads.
// CTA j owns units u0=4j..4j+3 (16 gate-cols), full K=512, all 64 b.
// - h read directly from L2 (__ldcg float4), 64-k double-buffered in regs
// - packed fma.rn.f32x2 over column pairs; weights ld.shared.v2.u64
// - c state in registers, one grid barrier per step
// ============================================================
__global__ void __launch_bounds__(RECTHR, 1) lstm_recurrent(
    const float* __restrict__ Whh,
    const float* __restrict__ h0,
    const float* __restrict__ c0,
    float* __restrict__ outSeq,   // layer1: [b][t][u]; layer0: null (writes g_H0T)
    float* __restrict__ hfin,
    float* __restrict__ cfin,
    int layer1)
{
    __shared__ float Wt[512 * 16];   // [k][16]  c = g*4 + j
    __shared__ float gsum[64 * 17];

    const int tid = threadIdx.x;
    const int bid = blockIdx.x;
    const int u0  = bid * 4;
    const int w   = tid >> 5;
    const int l   = tid & 31;
    const int bG  = w * 8 + (l >> 2);    // GEMM batch row
    const int cg  = l & 3;               // gate group (4 cols)
    const int bC  = tid & 63;            // cell batch
    const int uu  = tid >> 6;            // cell unit offset

    // persistent weight tile
    for (int e = tid; e < 16 * 512; e += RECTHR) {
        int c = e >> 9;
        int k = e & 511;
        int g = c >> 2, j = c & 3;
        Wt[k * 16 + c] = Whh[(size_t)(g * 512 + u0 + j) * 512 + k];
    }

    // init state
    {
        int idx = bid * RECTHR + tid;
        __stcg(&g_h[idx], h0[idx]);
    }
    float c_reg = c0[bC * HH + u0 + uu];

    const unsigned wsm0 = smem_u32(Wt) + (unsigned)cg * 16u;

    gridBarrier();

    for (int t = 0; t < TT; ++t) {
        const float* hRead = g_h + (t & 1) * 32768;
        float* hWrite      = g_h + ((t + 1) & 1) * 32768;
        const float* hrow  = hRead + bG * 512;

        unsigned long long a01 = 0ull, a23 = 0ull;   // {0.f,0.f} packed
        float4 bufA[16], bufB[16];

        auto loadChunk = [&](float4 (&dst)[16], int ch) {
            const float4* src = (const float4*)(hrow + ch * 64);
            #pragma unroll
            for (int i = 0; i < 16; ++i) dst[i] = __ldcg(src + i);
        };
        auto computeChunk = [&](const float4 (&cur)[16], int ch) {
            unsigned wb = wsm0 + (unsigned)ch * 4096u;
            #pragma unroll
            for (int i = 0; i < 16; ++i) {
                float4 hv = cur[i];
                #pragma unroll
                for (int kk = 0; kk < 4; ++kk) {
                    float h = (&hv.x)[kk];
                    unsigned long long hh, w01, w23;
                    asm("mov.b64 %0, {%1, %2};" : "=l"(hh) : "f"(h), "f"(h));
                    asm("ld.shared.v2.u64 {%0, %1}, [%2];"
                        : "=l"(w01), "=l"(w23)
                        : "r"(wb + (unsigned)((i * 4 + kk) * 64)));
                    asm("fma.rn.f32x2 %0, %1, %2, %0;" : "+l"(a01) : "l"(hh), "l"(w01));
                    asm("fma.rn.f32x2 %0, %1, %2, %0;" : "+l"(a23) : "l"(hh), "l"(w23));
                }
            }
        };

        loadChunk(bufA, 0);
        loadChunk(bufB, 1);
        #pragma unroll
        for (int c2 = 0; c2 < 3; ++c2) {
            computeChunk(bufA, 2 * c2);          // bufB load in flight
            loadChunk(bufA, 2 * c2 + 2);
            computeChunk(bufB, 2 * c2 + 1);      // bufA load in flight
            loadChunk(bufB, 2 * c2 + 3);
        }
        computeChunk(bufA, 6);
        computeChunk(bufB, 7);

        // write gate partials (cols cg*4 .. cg*4+3 of row bG)
        {
            float r0, r1, r2, r3;
            asm("mov.b64 {%0, %1}, %2;" : "=f"(r0), "=f"(r1) : "l"(a01));
            asm("mov.b64 {%0, %1}, %2;" : "=f"(r2), "=f"(r3) : "l"(a23));
            float* gs = gsum + bG * 17 + cg * 4;
            gs[0] = r0; gs[1] = r1; gs[2] = r2; gs[3] = r3;
        }
        __syncthreads();

        // ---- cell update (thread owns (bC, u0+uu); c in register) ----
        {
            float s[4];
            #pragma unroll
            for (int g = 0; g < 4; ++g) {
                float recur = gsum[bC * 17 + g * 4 + uu];
                float pre = __ldcs(g_G + (size_t)(g * 512 + u0 + uu) * 32768
                                       + (size_t)t * 64 + bC);
                s[g] = recur + pre;
            }
            float iv = sigmoidf_(s[0]);
            float fv = sigmoidf_(s[1]);
            float gv = tanhf(s[2]);
            float ov = sigmoidf_(s[3]);
            c_reg = fv * c_reg + iv * gv;
            float hv = ov * tanhf(c_reg);

            __stcg(&hWrite[bC * HH + u0 + uu], hv);
            if (layer1) outSeq[((size_t)bC * TT + t) * HH + u0 + uu] = hv;
            else        __stcg(&g_H0T[(size_t)(u0 + uu) * 32768 + (size_t)t * 64 + bC], hv);
            if (t == TT - 1) {
                hfin[bC * HH + u0 + uu] = hv;
                cfin[bC * HH + u0 + uu] = c_reg;
            }
        }
        gridBarrier();
    }
}

// ============================================================
// kernel_launch: 4 graph-capturable launches.
// Output: out [B,T,H] ++ h_fin [2,B,H] ++ c_fin [2,B,H]
// ============================================================
extern "C" void kernel_launch(void* const* d_in, const int* in_sizes, int n_in,
                              void* d_out, int out_size)
{
    (void)in_sizes; (void)n_in; (void)out_size;
    const float* x   = (const float*)d_in[0];
    const float* h0  = (const float*)d_in[1];
    const float* c0  = (const float*)d_in[2];
    const float* Wih = (const float*)d_in[3];
    const float* Whh = (const float*)d_in[4];
    const float* bih = (const float*)d_in[5];
    const float* bhh = (const float*)d_in[6];
    float* out  = (float*)d_out;
    float* hfin = out + (size_t)BB * TT * HH;
    float* cfin = hfin + 2 * BB * HH;

    dim3 pgrid(32768 / 128, GG / 128);   // (256, 16)

    // layer 0
    lstm_pregemm<<<pgrid, 256>>>(x, Wih, bih, bhh, 1);
    lstm_recurrent<<<RECBLK, RECTHR>>>(Whh, h0, c0, nullptr, hfin, cfin, 0);
    // layer 1 (input GEMM reads g_H0T directly)
    lstm_pregemm<<<pgrid, 256>>>(x, Wih + (size_t)GG * 512, bih + GG, bhh + GG, 0);
    lstm_recurrent<<<RECBLK, RECTHR>>>(Whh + (size_t)GG * 512,
                                       h0 + BB * HH, c0 + BB * HH,
                                       out, hfin + BB * HH, cfin + BB * HH, 1);
}